// round 1
// baseline (speedup 1.0000x reference)
#include <cuda_runtime.h>

#define NA 100000
#define NB 100000
#define NE 1600000
#define DREL 128
#define KDIM 256

// Scratch degree accumulators (allocation-free scratch per harness rules).
__device__ float g_deg1[NB];
__device__ float g_deg2[NA];

// ---------------------------------------------------------------------------
// Zero-init: dst1/dst2 output regions + degree arrays. Re-run every call so
// graph replays are deterministic.
// ---------------------------------------------------------------------------
__global__ __launch_bounds__(256) void zero_out_kernel(float4* __restrict__ dst1,
                                                       float4* __restrict__ dst2,
                                                       int n4each) {
    int i = blockIdx.x * blockDim.x + threadIdx.x;
    float4 z = make_float4(0.f, 0.f, 0.f, 0.f);
    if (i < n4each) {
        dst1[i] = z;
        dst2[i] = z;
    }
    if (i < NB) g_deg1[i] = 0.f;
    if (i < NA) g_deg2[i] = 0.f;
}

// ---------------------------------------------------------------------------
// FP32 SIMT GEMM: C[m][n] = sum_k X[m][k] * W[n][k]
//   X: [M, 256] row-major, W: [128, 256] row-major, C: [M, 128]
// Block tile 128x128, 256 threads, 8x8 per-thread tile, K-chunk 8,
// double-buffered SMEM with register prefetch.
// blockIdx.y selects (x_a,W_a,xp_a) vs (x_b,W_b,xp_b).
// ---------------------------------------------------------------------------
__global__ __launch_bounds__(256, 2) void gemm_kernel(
    const float* __restrict__ x_a, const float* __restrict__ x_b,
    const float* __restrict__ W_a, const float* __restrict__ W_b,
    float* __restrict__ xp_a, float* __restrict__ xp_b) {
    const float* X;
    const float* W;
    float* C;
    if (blockIdx.y == 0) { X = x_a; W = W_a; C = xp_a; }
    else                 { X = x_b; W = W_b; C = xp_b; }
    const int M = NA;  // == NB

    __shared__ float As[2][8][128];  // As[buf][k][m]
    __shared__ float Bs[2][8][128];  // Bs[buf][k][n]

    const int t = threadIdx.x;
    const int m0 = blockIdx.x * 128;

    // Global->SMEM load mapping: each thread loads one float4 along K.
    const int lrow = t >> 1;         // 0..127 (row of X tile / row n of W)
    const int lk   = (t & 1) * 4;    // 0 or 4 within the 8-wide K chunk
    // Compute mapping: 16x16 thread grid; fragments strided by 64 for
    // conflict-free LDS.128.
    const int tx = t & 15;
    const int ty = t >> 4;

    float c[8][8];
#pragma unroll
    for (int i = 0; i < 8; ++i)
#pragma unroll
        for (int j = 0; j < 8; ++j) c[i][j] = 0.f;

    const int grow = m0 + lrow;
    const bool rvalid = (grow < M);

    // Prologue: load K-chunk 0 into buffer 0.
    float4 a0 = make_float4(0.f, 0.f, 0.f, 0.f);
    if (rvalid) a0 = *(const float4*)(X + (size_t)grow * KDIM + lk);
    float4 b0 = *(const float4*)(W + (size_t)lrow * KDIM + lk);
    As[0][lk + 0][lrow] = a0.x; As[0][lk + 1][lrow] = a0.y;
    As[0][lk + 2][lrow] = a0.z; As[0][lk + 3][lrow] = a0.w;
    Bs[0][lk + 0][lrow] = b0.x; Bs[0][lk + 1][lrow] = b0.y;
    Bs[0][lk + 2][lrow] = b0.z; Bs[0][lk + 3][lrow] = b0.w;
    __syncthreads();

    int buf = 0;
#pragma unroll 1
    for (int kt = 0; kt < KDIM / 8; ++kt) {
        float4 an = make_float4(0.f, 0.f, 0.f, 0.f);
        float4 bn = make_float4(0.f, 0.f, 0.f, 0.f);
        if (kt + 1 < KDIM / 8) {
            const int k0 = (kt + 1) * 8 + lk;
            if (rvalid) an = *(const float4*)(X + (size_t)grow * KDIM + k0);
            bn = *(const float4*)(W + (size_t)lrow * KDIM + k0);
        }

#pragma unroll
        for (int kk = 0; kk < 8; ++kk) {
            const float4 aA0 = *(const float4*)&As[buf][kk][ty * 4];
            const float4 aA1 = *(const float4*)&As[buf][kk][64 + ty * 4];
            const float4 bB0 = *(const float4*)&Bs[buf][kk][tx * 4];
            const float4 bB1 = *(const float4*)&Bs[buf][kk][64 + tx * 4];
            const float av[8] = {aA0.x, aA0.y, aA0.z, aA0.w,
                                 aA1.x, aA1.y, aA1.z, aA1.w};
            const float bv[8] = {bB0.x, bB0.y, bB0.z, bB0.w,
                                 bB1.x, bB1.y, bB1.z, bB1.w};
#pragma unroll
            for (int mi = 0; mi < 8; ++mi)
#pragma unroll
                for (int ni = 0; ni < 8; ++ni)
                    c[mi][ni] += av[mi] * bv[ni];
        }

        if (kt + 1 < KDIM / 8) {
            const int nb = buf ^ 1;
            As[nb][lk + 0][lrow] = an.x; As[nb][lk + 1][lrow] = an.y;
            As[nb][lk + 2][lrow] = an.z; As[nb][lk + 3][lrow] = an.w;
            Bs[nb][lk + 0][lrow] = bn.x; Bs[nb][lk + 1][lrow] = bn.y;
            Bs[nb][lk + 2][lrow] = bn.z; Bs[nb][lk + 3][lrow] = bn.w;
            __syncthreads();
            buf = nb;
        }
    }

    // Epilogue: write 8 rows x 2 float4 per thread.
#pragma unroll
    for (int g = 0; g < 2; ++g) {
#pragma unroll
        for (int i = 0; i < 4; ++i) {
            const int r = m0 + g * 64 + ty * 4 + i;
            if (r < M) {
                const int mi = g * 4 + i;
                *(float4*)(C + (size_t)r * DREL + tx * 4) =
                    make_float4(c[mi][0], c[mi][1], c[mi][2], c[mi][3]);
                *(float4*)(C + (size_t)r * DREL + 64 + tx * 4) =
                    make_float4(c[mi][4], c[mi][5], c[mi][6], c[mi][7]);
            }
        }
    }
}

// ---------------------------------------------------------------------------
// Scatter-add: one warp per edge. Gather a full 512B row of xp[src], RED.v4
// into acc[dst]. Lane 0 also counts the degree. Grid-stride over 2*NE edges:
// first NE edges are type1 (a->b), rest type2 (b->a) — keeps the L2 working
// set to (xp_a + dst1) then (xp_b + dst2), each ~103 MB < 126 MB L2.
// ---------------------------------------------------------------------------
__global__ __launch_bounds__(256) void scatter_kernel(
    const int* __restrict__ ei1, const int* __restrict__ ei2,
    const float* __restrict__ xp_a, const float* __restrict__ xp_b,
    float* __restrict__ dst1, float* __restrict__ dst2) {
    const long wid = (long)(blockIdx.x * blockDim.x + threadIdx.x) >> 5;
    const int lane = threadIdx.x & 31;
    const long nwarps = ((long)gridDim.x * blockDim.x) >> 5;

    for (long e = wid; e < 2L * NE; e += nwarps) {
        const int* ei;
        const float* xp;
        float* acc;
        float* deg;
        long ee;
        if (e < NE) { ei = ei1; xp = xp_a; acc = dst1; deg = g_deg1; ee = e; }
        else        { ei = ei2; xp = xp_b; acc = dst2; deg = g_deg2; ee = e - NE; }

        const int src = __ldg(ei + ee);
        const int dst = __ldg(ei + NE + ee);

        const float4 v = *(const float4*)(xp + (size_t)src * DREL + lane * 4);
        float* ap = acc + (size_t)dst * DREL + lane * 4;
        asm volatile("red.global.add.v4.f32 [%0], {%1, %2, %3, %4};"
                     :: "l"(ap), "f"(v.x), "f"(v.y), "f"(v.z), "f"(v.w)
                     : "memory");
        if (lane == 0) atomicAdd(deg + dst, 1.0f);
    }
}

// ---------------------------------------------------------------------------
// Divide by clamped degree (in place).
// ---------------------------------------------------------------------------
__global__ __launch_bounds__(256) void divide_kernel(float4* __restrict__ dst1,
                                                     float4* __restrict__ dst2) {
    const int i = blockIdx.x * blockDim.x + threadIdx.x;
    const int n4 = NB * (DREL / 4);
    if (i < n4) {
        const int row = i >> 5;  // DREL/4 = 32 float4 per row
        {
            const float inv = 1.f / fmaxf(g_deg1[row], 1.f);
            float4 v = dst1[i];
            v.x *= inv; v.y *= inv; v.z *= inv; v.w *= inv;
            dst1[i] = v;
        }
        {
            const float inv = 1.f / fmaxf(g_deg2[row], 1.f);
            float4 v = dst2[i];
            v.x *= inv; v.y *= inv; v.z *= inv; v.w *= inv;
            dst2[i] = v;
        }
    }
}

// ---------------------------------------------------------------------------
// Launch. Output layout (reference return order, flattened):
//   [ dst1 (NB*128) | xp_a (NA*128) | dst2 (NA*128) | xp_b (NB*128) ]
// ---------------------------------------------------------------------------
extern "C" void kernel_launch(void* const* d_in, const int* in_sizes, int n_in,
                              void* d_out, int out_size) {
    const float* x_a = (const float*)d_in[0];
    const float* x_b = (const float*)d_in[1];
    const float* W_a = (const float*)d_in[2];
    const float* W_b = (const float*)d_in[3];
    const int* ei1   = (const int*)d_in[4];
    const int* ei2   = (const int*)d_in[5];

    float* out  = (float*)d_out;
    float* dst1 = out;
    float* xp_a = dst1 + (size_t)NB * DREL;
    float* dst2 = xp_a + (size_t)NA * DREL;
    float* xp_b = dst2 + (size_t)NA * DREL;

    const int n4each = NB * (DREL / 4);           // 3,200,000 float4
    const int zblocks = (n4each + 255) / 256;     // 12500

    zero_out_kernel<<<zblocks, 256>>>((float4*)dst1, (float4*)dst2, n4each);

    dim3 ggrid((NA + 127) / 128, 2);
    gemm_kernel<<<ggrid, 256>>>(x_a, x_b, W_a, W_b, xp_a, xp_b);

    scatter_kernel<<<4736, 256>>>(ei1, ei2, xp_a, xp_b, dst1, dst2);

    divide_kernel<<<zblocks, 256>>>((float4*)dst1, (float4*)dst2);
}

// round 3
// speedup vs baseline: 1.1938x; 1.1938x over previous
#include <cuda_runtime.h>

#define NA 100000
#define NB 100000
#define NE 1600000
#define DREL 128
#define KDIM 256

// ---------------------------------------------------------------------------
// Device scratch (allocation-free per harness rules).
// CSR per edge type: counts -> row_start (exclusive scan) -> csr_src fill.
// ---------------------------------------------------------------------------
__device__ int g_counts1[NB];
__device__ int g_counts2[NA];
__device__ int g_rowstart1[NB + 1];
__device__ int g_rowstart2[NA + 1];
__device__ int g_cursor1[NB];
__device__ int g_cursor2[NA];
__device__ int g_csr1[NE];
__device__ int g_csr2[NE];

// ---------------------------------------------------------------------------
// Zero histogram counters (graph-replay deterministic).
// ---------------------------------------------------------------------------
__global__ __launch_bounds__(256) void zero_counts_kernel() {
    const int i = blockIdx.x * blockDim.x + threadIdx.x;
    if (i < NB) g_counts1[i] = 0;
    if (i < NA) g_counts2[i] = 0;
}

// ---------------------------------------------------------------------------
// Degree histogram over both edge types.
// ---------------------------------------------------------------------------
__global__ __launch_bounds__(256) void histogram_kernel(
    const int* __restrict__ ei1, const int* __restrict__ ei2) {
    const int i = blockIdx.x * blockDim.x + threadIdx.x;
    if (i < NE) {
        atomicAdd(&g_counts1[__ldg(ei1 + NE + i)], 1);
        atomicAdd(&g_counts2[__ldg(ei2 + NE + i)], 1);
    }
}

// ---------------------------------------------------------------------------
// Exclusive scan of counts -> row_start (+cursor copy). One block per type,
// 1024 threads, chunked serial scan + Hillis-Steele across thread partials.
// ---------------------------------------------------------------------------
__global__ __launch_bounds__(1024) void scan_kernel() {
    const int type = blockIdx.x;
    const int* counts = type ? g_counts2 : g_counts1;
    int* rowstart = type ? g_rowstart2 : g_rowstart1;
    int* cursor = type ? g_cursor2 : g_cursor1;
    const int N = type ? NA : NB;

    const int tid = threadIdx.x;
    const int chunk = (N + 1023) / 1024;
    const int lo = tid * chunk;
    const int hi = min(lo + chunk, N);

    int sum = 0;
    for (int i = lo; i < hi; ++i) sum += counts[i];

    __shared__ int sh[1024];
    sh[tid] = sum;
    __syncthreads();
#pragma unroll
    for (int off = 1; off < 1024; off <<= 1) {
        int v = 0;
        if (tid >= off) v = sh[tid - off];
        __syncthreads();
        if (tid >= off) sh[tid] += v;
        __syncthreads();
    }
    int run = sh[tid] - sum;  // exclusive prefix

    for (int i = lo; i < hi; ++i) {
        rowstart[i] = run;
        cursor[i] = run;
        run += counts[i];
    }
    if (tid == 1023) rowstart[N] = run;  // == NE (total)
}

// ---------------------------------------------------------------------------
// CSR fill: scatter src indices into per-dst buckets.
// ---------------------------------------------------------------------------
__global__ __launch_bounds__(256) void fill_kernel(
    const int* __restrict__ ei1, const int* __restrict__ ei2) {
    const int i = blockIdx.x * blockDim.x + threadIdx.x;
    if (i < NE) {
        {
            const int src = __ldg(ei1 + i);
            const int dst = __ldg(ei1 + NE + i);
            const int idx = atomicAdd(&g_cursor1[dst], 1);
            g_csr1[idx] = src;
        }
        {
            const int src = __ldg(ei2 + i);
            const int dst = __ldg(ei2 + NE + i);
            const int idx = atomicAdd(&g_cursor2[dst], 1);
            g_csr2[idx] = src;
        }
    }
}

// ---------------------------------------------------------------------------
// FP32 SIMT GEMM: C[m][n] = sum_k X[m][k] * W[n][k]
// Block tile 128x128, 256 threads, 8x8 thread tile, K-chunk 8, double-buffered.
// blockIdx.y selects (x_a,W_a,xp_a) vs (x_b,W_b,xp_b).
// ---------------------------------------------------------------------------
__global__ __launch_bounds__(256, 2) void gemm_kernel(
    const float* __restrict__ x_a, const float* __restrict__ x_b,
    const float* __restrict__ W_a, const float* __restrict__ W_b,
    float* __restrict__ xp_a, float* __restrict__ xp_b) {
    const float* X;
    const float* W;
    float* C;
    if (blockIdx.y == 0) { X = x_a; W = W_a; C = xp_a; }
    else                 { X = x_b; W = W_b; C = xp_b; }
    const int M = NA;

    __shared__ float As[2][8][128];
    __shared__ float Bs[2][8][128];

    const int t = threadIdx.x;
    const int m0 = blockIdx.x * 128;
    const int lrow = t >> 1;
    const int lk = (t & 1) * 4;
    const int tx = t & 15;
    const int ty = t >> 4;

    float c[8][8];
#pragma unroll
    for (int i = 0; i < 8; ++i)
#pragma unroll
        for (int j = 0; j < 8; ++j) c[i][j] = 0.f;

    const int grow = m0 + lrow;
    const bool rvalid = (grow < M);

    float4 a0 = make_float4(0.f, 0.f, 0.f, 0.f);
    if (rvalid) a0 = *(const float4*)(X + (size_t)grow * KDIM + lk);
    float4 b0 = *(const float4*)(W + (size_t)lrow * KDIM + lk);
    As[0][lk + 0][lrow] = a0.x; As[0][lk + 1][lrow] = a0.y;
    As[0][lk + 2][lrow] = a0.z; As[0][lk + 3][lrow] = a0.w;
    Bs[0][lk + 0][lrow] = b0.x; Bs[0][lk + 1][lrow] = b0.y;
    Bs[0][lk + 2][lrow] = b0.z; Bs[0][lk + 3][lrow] = b0.w;
    __syncthreads();

    int buf = 0;
#pragma unroll 1
    for (int kt = 0; kt < KDIM / 8; ++kt) {
        float4 an = make_float4(0.f, 0.f, 0.f, 0.f);
        float4 bn = make_float4(0.f, 0.f, 0.f, 0.f);
        if (kt + 1 < KDIM / 8) {
            const int k0 = (kt + 1) * 8 + lk;
            if (rvalid) an = *(const float4*)(X + (size_t)grow * KDIM + k0);
            bn = *(const float4*)(W + (size_t)lrow * KDIM + k0);
        }

#pragma unroll
        for (int kk = 0; kk < 8; ++kk) {
            const float4 aA0 = *(const float4*)&As[buf][kk][ty * 4];
            const float4 aA1 = *(const float4*)&As[buf][kk][64 + ty * 4];
            const float4 bB0 = *(const float4*)&Bs[buf][kk][tx * 4];
            const float4 bB1 = *(const float4*)&Bs[buf][kk][64 + tx * 4];
            const float av[8] = {aA0.x, aA0.y, aA0.z, aA0.w,
                                 aA1.x, aA1.y, aA1.z, aA1.w};
            const float bv[8] = {bB0.x, bB0.y, bB0.z, bB0.w,
                                 bB1.x, bB1.y, bB1.z, bB1.w};
#pragma unroll
            for (int mi = 0; mi < 8; ++mi)
#pragma unroll
                for (int ni = 0; ni < 8; ++ni)
                    c[mi][ni] += av[mi] * bv[ni];
        }

        if (kt + 1 < KDIM / 8) {
            const int nb = buf ^ 1;
            As[nb][lk + 0][lrow] = an.x; As[nb][lk + 1][lrow] = an.y;
            As[nb][lk + 2][lrow] = an.z; As[nb][lk + 3][lrow] = an.w;
            Bs[nb][lk + 0][lrow] = bn.x; Bs[nb][lk + 1][lrow] = bn.y;
            Bs[nb][lk + 2][lrow] = bn.z; Bs[nb][lk + 3][lrow] = bn.w;
            __syncthreads();
            buf = nb;
        }
    }

#pragma unroll
    for (int g = 0; g < 2; ++g) {
#pragma unroll
        for (int i = 0; i < 4; ++i) {
            const int r = m0 + g * 64 + ty * 4 + i;
            if (r < M) {
                const int mi = g * 4 + i;
                *(float4*)(C + (size_t)r * DREL + tx * 4) =
                    make_float4(c[mi][0], c[mi][1], c[mi][2], c[mi][3]);
                *(float4*)(C + (size_t)r * DREL + 64 + tx * 4) =
                    make_float4(c[mi][4], c[mi][5], c[mi][6], c[mi][7]);
            }
        }
    }
}

// ---------------------------------------------------------------------------
// Atomic-free aggregation: one warp per destination row. Gather all neighbor
// rows (avg degree 16) from L2-resident xp, accumulate in registers (float4
// per lane = 128 floats per warp), scale by 1/max(deg,1), write once.
// Warps [0, NB) handle type1, [NB, NB+NA) handle type2.
// ---------------------------------------------------------------------------
__global__ __launch_bounds__(256) void aggregate_kernel(
    const float* __restrict__ xp_a, const float* __restrict__ xp_b,
    float* __restrict__ dst1, float* __restrict__ dst2) {
    const int gw = (blockIdx.x * blockDim.x + threadIdx.x) >> 5;
    const int lane = threadIdx.x & 31;
    if (gw >= NA + NB) return;

    const int* rowstart;
    const int* csr;
    const float* xp;
    float* outp;
    int r;
    if (gw < NB) { r = gw;      rowstart = g_rowstart1; csr = g_csr1; xp = xp_a; outp = dst1; }
    else         { r = gw - NB; rowstart = g_rowstart2; csr = g_csr2; xp = xp_b; outp = dst2; }

    const int beg = __ldg(rowstart + r);
    const int end = __ldg(rowstart + r + 1);
    const int deg = end - beg;

    float4 acc0 = make_float4(0.f, 0.f, 0.f, 0.f);
    float4 acc1 = make_float4(0.f, 0.f, 0.f, 0.f);

    int i = beg;
    for (; i + 1 < end; i += 2) {
        const int s0 = __ldg(csr + i);
        const int s1 = __ldg(csr + i + 1);
        const float4 v0 = *(const float4*)(xp + (size_t)s0 * DREL + lane * 4);
        const float4 v1 = *(const float4*)(xp + (size_t)s1 * DREL + lane * 4);
        acc0.x += v0.x; acc0.y += v0.y; acc0.z += v0.z; acc0.w += v0.w;
        acc1.x += v1.x; acc1.y += v1.y; acc1.z += v1.z; acc1.w += v1.w;
    }
    if (i < end) {
        const int s0 = __ldg(csr + i);
        const float4 v0 = *(const float4*)(xp + (size_t)s0 * DREL + lane * 4);
        acc0.x += v0.x; acc0.y += v0.y; acc0.z += v0.z; acc0.w += v0.w;
    }

    const float inv = 1.f / fmaxf((float)deg, 1.f);
    float4 res;
    res.x = (acc0.x + acc1.x) * inv;
    res.y = (acc0.y + acc1.y) * inv;
    res.z = (acc0.z + acc1.z) * inv;
    res.w = (acc0.w + acc1.w) * inv;
    *(float4*)(outp + (size_t)r * DREL + lane * 4) = res;
}

// ---------------------------------------------------------------------------
// Launch. Output layout (reference return order, flattened):
//   [ dst1 (NB*128) | xp_a (NA*128) | dst2 (NA*128) | xp_b (NB*128) ]
// ---------------------------------------------------------------------------
extern "C" void kernel_launch(void* const* d_in, const int* in_sizes, int n_in,
                              void* d_out, int out_size) {
    const float* x_a = (const float*)d_in[0];
    const float* x_b = (const float*)d_in[1];
    const float* W_a = (const float*)d_in[2];
    const float* W_b = (const float*)d_in[3];
    const int* ei1   = (const int*)d_in[4];
    const int* ei2   = (const int*)d_in[5];

    float* out  = (float*)d_out;
    float* dst1 = out;
    float* xp_a = dst1 + (size_t)NB * DREL;
    float* dst2 = xp_a + (size_t)NA * DREL;
    float* xp_b = dst2 + (size_t)NA * DREL;

    zero_counts_kernel<<<(NA + 255) / 256, 256>>>();
    histogram_kernel<<<(NE + 255) / 256, 256>>>(ei1, ei2);
    scan_kernel<<<2, 1024>>>();
    fill_kernel<<<(NE + 255) / 256, 256>>>(ei1, ei2);

    dim3 ggrid((NA + 127) / 128, 2);
    gemm_kernel<<<ggrid, 256>>>(x_a, x_b, W_a, W_b, xp_a, xp_b);

    const int nwarps = NA + NB;
    aggregate_kernel<<<(nwarps * 32 + 255) / 256, 256>>>(xp_a, xp_b, dst1, dst2);
}